// round 2
// baseline (speedup 1.0000x reference)
#include <cuda_runtime.h>
#include <math.h>

#define M_TOT   16384
#define DM      1024
#define DFF_    4096

// ---------------- scratch ----------------
// h,q,k,v,attn,x1: 6 x 16M floats; ff: 128M; gated: 64M; kv: 256K; kvp: 2M
#define OFF_H     0ull
#define OFF_Q     16777216ull
#define OFF_K     33554432ull
#define OFF_V     50331648ull
#define OFF_ATTN  67108864ull
#define OFF_X1    83886080ull
#define OFF_FF    100663296ull
#define OFF_GATED 234881024ull
#define OFF_KV    301989888ull
#define OFF_KVP   302252032ull
#define SCRATCH_TOT 304349184ull

__device__ __align__(16) float g_scratch[SCRATCH_TOT];

// ---------------- layernorm ----------------
__global__ __launch_bounds__(256) void ln_k(const float* __restrict__ x,
                                            const float* __restrict__ gamma,
                                            const float* __restrict__ beta,
                                            float* __restrict__ out)
{
    int row = blockIdx.x, tid = threadIdx.x;
    const float4* xr = (const float4*)(x + (size_t)row * DM);
    float4 v = xr[tid];
    float s  = v.x + v.y + v.z + v.w;
    float ss = v.x*v.x + v.y*v.y + v.z*v.z + v.w*v.w;
    #pragma unroll
    for (int o = 16; o; o >>= 1) {
        s  += __shfl_xor_sync(0xffffffffu, s,  o);
        ss += __shfl_xor_sync(0xffffffffu, ss, o);
    }
    __shared__ float shs[8], shss[8];
    __shared__ float smu, srs;
    int w = tid >> 5, lane = tid & 31;
    if (lane == 0) { shs[w] = s; shss[w] = ss; }
    __syncthreads();
    if (tid == 0) {
        float ts = 0.f, tss = 0.f;
        #pragma unroll
        for (int i = 0; i < 8; i++) { ts += shs[i]; tss += shss[i]; }
        float mu  = ts * (1.0f / DM);
        float var = tss * (1.0f / DM) - mu * mu;
        smu = mu;
        srs = rsqrtf(var + 1e-5f);
    }
    __syncthreads();
    float mu = smu, rs = srs;
    float4 g = ((const float4*)gamma)[tid];
    float4 b = ((const float4*)beta)[tid];
    float4 o;
    o.x = (v.x - mu) * rs * g.x + b.x;
    o.y = (v.y - mu) * rs * g.y + b.y;
    o.z = (v.z - mu) * rs * g.z + b.z;
    o.w = (v.w - mu) * rs * g.w + b.w;
    ((float4*)(out + (size_t)row * DM))[tid] = o;
}

// ---------------- tiled fp32 GEMM: C = A[MxK] @ B[KxN] + bias (+epilogue) --------
// EPI: 0 = bias only, 1 = bias + (elu(x)+1), 2 = bias + residual R
template<int EPI>
__global__ __launch_bounds__(256) void gemm_k(const float* __restrict__ A,
                                              const float* __restrict__ B,
                                              const float* __restrict__ bias,
                                              const float* __restrict__ R,
                                              float* __restrict__ C,
                                              int M, int N, int K)
{
    __shared__ float As[8][128];   // transposed A tile
    __shared__ float Bs[8][128];
    int tid = threadIdx.x;
    int tx = tid & 15, ty = tid >> 4;
    const float* Ab = A + (size_t)blockIdx.y * 128 * K;
    const float* Bb = B + blockIdx.x * 128;
    int arow = tid >> 1, acol = (tid & 1) * 4;
    int brow = tid >> 5, bcol = (tid & 31) * 4;
    float acc[8][8];
    #pragma unroll
    for (int i = 0; i < 8; i++)
        #pragma unroll
        for (int j = 0; j < 8; j++) acc[i][j] = 0.f;

    for (int k0 = 0; k0 < K; k0 += 8) {
        float4 a4 = *(const float4*)(Ab + (size_t)arow * K + k0 + acol);
        As[acol + 0][arow] = a4.x;
        As[acol + 1][arow] = a4.y;
        As[acol + 2][arow] = a4.z;
        As[acol + 3][arow] = a4.w;
        *(float4*)&Bs[brow][bcol] = *(const float4*)(Bb + (size_t)(k0 + brow) * N + bcol);
        __syncthreads();
        #pragma unroll
        for (int kk = 0; kk < 8; kk++) {
            float4 a0 = *(const float4*)&As[kk][ty * 8];
            float4 a1 = *(const float4*)&As[kk][ty * 8 + 4];
            float4 b0 = *(const float4*)&Bs[kk][tx * 8];
            float4 b1 = *(const float4*)&Bs[kk][tx * 8 + 4];
            float af[8] = {a0.x,a0.y,a0.z,a0.w,a1.x,a1.y,a1.z,a1.w};
            float bf[8] = {b0.x,b0.y,b0.z,b0.w,b1.x,b1.y,b1.z,b1.w};
            #pragma unroll
            for (int i = 0; i < 8; i++)
                #pragma unroll
                for (int j = 0; j < 8; j++)
                    acc[i][j] += af[i] * bf[j];
        }
        __syncthreads();
    }

    int row0 = blockIdx.y * 128 + ty * 8;
    int col0 = blockIdx.x * 128 + tx * 8;
    #pragma unroll
    for (int i = 0; i < 8; i++) {
        size_t base = (size_t)(row0 + i) * N + col0;
        #pragma unroll
        for (int j = 0; j < 8; j += 4) {
            float4 bb = *(const float4*)(bias + col0 + j);
            float vals[4];
            vals[0] = acc[i][j + 0] + bb.x;
            vals[1] = acc[i][j + 1] + bb.y;
            vals[2] = acc[i][j + 2] + bb.z;
            vals[3] = acc[i][j + 3] + bb.w;
            if (EPI == 1) {
                #pragma unroll
                for (int t = 0; t < 4; t++)
                    vals[t] = (vals[t] > 0.f) ? (vals[t] + 1.f) : expf(vals[t]);
            }
            if (EPI == 2) {
                float4 rr = *(const float4*)(R + base + j);
                vals[0] += rr.x; vals[1] += rr.y; vals[2] += rr.z; vals[3] += rr.w;
            }
            *(float4*)(C + base + j) = make_float4(vals[0], vals[1], vals[2], vals[3]);
        }
    }
}

// ---------------- kv = sum_s k[s,d] v[s,e] per (b,h), split over S --------------
__global__ __launch_bounds__(256) void kv_partial_k(const float* __restrict__ Kp,
                                                    const float* __restrict__ Vp,
                                                    float* __restrict__ kvp)
{
    int bh = blockIdx.x, sp = blockIdx.y;     // bh: 0..63, sp: 0..7
    int b = bh >> 4, h = bh & 15;
    int tid = threadIdx.x;
    __shared__ float ks[32][64];
    __shared__ float vs[32][64];
    float acc[4][4];
    #pragma unroll
    for (int i = 0; i < 4; i++)
        #pragma unroll
        for (int j = 0; j < 4; j++) acc[i][j] = 0.f;

    int d0 = (tid >> 4) * 4, e0 = (tid & 15) * 4;
    size_t base = ((size_t)b * 4096) * DM + h * 64;
    for (int s0 = sp * 512; s0 < sp * 512 + 512; s0 += 32) {
        #pragma unroll
        for (int i = 0; i < 2; i++) {
            int f = tid + i * 256;
            int r = f >> 4, c = (f & 15) * 4;
            size_t off = base + (size_t)(s0 + r) * DM + c;
            *(float4*)&ks[r][c] = *(const float4*)(Kp + off);
            *(float4*)&vs[r][c] = *(const float4*)(Vp + off);
        }
        __syncthreads();
        #pragma unroll
        for (int ssm = 0; ssm < 32; ssm++) {
            float4 kd4 = *(const float4*)&ks[ssm][d0];
            float4 ve4 = *(const float4*)&vs[ssm][e0];
            float kd[4] = {kd4.x, kd4.y, kd4.z, kd4.w};
            float ve[4] = {ve4.x, ve4.y, ve4.z, ve4.w};
            #pragma unroll
            for (int i = 0; i < 4; i++)
                #pragma unroll
                for (int j = 0; j < 4; j++)
                    acc[i][j] += kd[i] * ve[j];
        }
        __syncthreads();
    }
    float* outp = kvp + ((size_t)sp * 64 + bh) * 4096;
    #pragma unroll
    for (int i = 0; i < 4; i++)
        *(float4*)(outp + (d0 + i) * 64 + e0) =
            make_float4(acc[i][0], acc[i][1], acc[i][2], acc[i][3]);
}

__global__ __launch_bounds__(256) void kv_reduce_k(const float* __restrict__ kvp,
                                                   float* __restrict__ kv)
{
    int i = blockIdx.x * 256 + threadIdx.x;   // < 64*4096
    float s = 0.f;
    #pragma unroll
    for (int sp = 0; sp < 8; sp++) s += kvp[(size_t)sp * 262144 + i];
    kv[i] = s;
}

// ---------------- attn[s,e] = sum_d q[s,d] kv[d,e] per (b,h) --------------------
__global__ __launch_bounds__(256) void attn_k(const float* __restrict__ Q,
                                              const float* __restrict__ KV,
                                              float* __restrict__ O)
{
    int bh = blockIdx.x, st = blockIdx.y;
    int b = bh >> 4, h = bh & 15;
    int tid = threadIdx.x;
    __shared__ float kvs[64][64];
    __shared__ float qs[64][68];   // padded vs bank conflicts
    const float* kvsrc = KV + (size_t)bh * 4096;
    #pragma unroll
    for (int i = 0; i < 4; i++) {
        int f = tid + i * 256;
        int r = f >> 4, c = (f & 15) * 4;
        *(float4*)&kvs[r][c] = *(const float4*)(kvsrc + r * 64 + c);
    }
    size_t qbase = ((size_t)b * 4096 + st * 64) * DM + h * 64;
    #pragma unroll
    for (int i = 0; i < 4; i++) {
        int f = tid + i * 256;
        int r = f >> 4, c = (f & 15) * 4;
        *(float4*)&qs[r][c] = *(const float4*)(Q + qbase + (size_t)r * DM + c);
    }
    __syncthreads();
    int r = tid >> 2, e0 = (tid & 3) * 16;
    float acc[16];
    #pragma unroll
    for (int j = 0; j < 16; j++) acc[j] = 0.f;
    #pragma unroll 8
    for (int d = 0; d < 64; d++) {
        float qd = qs[r][d];
        #pragma unroll
        for (int j = 0; j < 16; j++) acc[j] += qd * kvs[d][e0 + j];
    }
    float* orow = O + qbase + (size_t)r * DM + e0;
    #pragma unroll
    for (int j = 0; j < 16; j += 4)
        *(float4*)(orow + j) = make_float4(acc[j], acc[j+1], acc[j+2], acc[j+3]);
}

// ---------------- geglu: out = gelu_exact(ff[:,:4096]) * ff[:,4096:] ------------
__global__ __launch_bounds__(256) void geglu_k(const float* __restrict__ ff,
                                               float* __restrict__ out)
{
    size_t m = blockIdx.x;
    int tid = threadIdx.x;
    const float4* gp = (const float4*)(ff + m * 8192);
    const float4* lp = (const float4*)(ff + m * 8192 + 4096);
    float4* op = (float4*)(out + m * 4096);
    const float inv_sqrt2 = 0.70710678118654752f;
    #pragma unroll
    for (int i = 0; i < 4; i++) {
        int idx = tid + i * 256;
        float4 g = gp[idx], l = lp[idx];
        float4 o;
        o.x = 0.5f * g.x * (1.f + erff(g.x * inv_sqrt2)) * l.x;
        o.y = 0.5f * g.y * (1.f + erff(g.y * inv_sqrt2)) * l.y;
        o.z = 0.5f * g.z * (1.f + erff(g.z * inv_sqrt2)) * l.z;
        o.w = 0.5f * g.w * (1.f + erff(g.w * inv_sqrt2)) * l.w;
        op[idx] = o;
    }
}

// ---------------- launch ----------------
extern "C" void kernel_launch(void* const* d_in, const int* in_sizes, int n_in,
                              void* d_out, int out_size)
{
    const float* x   = (const float*)d_in[0];
    const float* wq  = (const float*)d_in[1];
    const float* bq  = (const float*)d_in[2];
    const float* wk  = (const float*)d_in[3];
    const float* bk  = (const float*)d_in[4];
    const float* wv  = (const float*)d_in[5];
    const float* bv  = (const float*)d_in[6];
    const float* wo  = (const float*)d_in[7];
    const float* bo  = (const float*)d_in[8];
    const float* w1  = (const float*)d_in[9];
    const float* b1  = (const float*)d_in[10];
    const float* w2  = (const float*)d_in[11];
    const float* b2  = (const float*)d_in[12];
    const float* g1  = (const float*)d_in[13];
    const float* be1 = (const float*)d_in[14];
    const float* g2  = (const float*)d_in[15];
    const float* be2 = (const float*)d_in[16];
    float* out = (float*)d_out;

    void* sp = nullptr;
    cudaGetSymbolAddress(&sp, g_scratch);
    float* S     = (float*)sp;
    float* h     = S + OFF_H;
    float* q     = S + OFF_Q;
    float* k     = S + OFF_K;
    float* v     = S + OFF_V;
    float* attn  = S + OFF_ATTN;
    float* x1    = S + OFF_X1;
    float* ffb   = S + OFF_FF;
    float* gated = S + OFF_GATED;
    float* kv    = S + OFF_KV;
    float* kvp   = S + OFF_KVP;

    dim3 g1024(DM / 128, M_TOT / 128);      // (8, 128)
    dim3 g8192((2 * DFF_) / 128, M_TOT / 128); // (64, 128)

    // 1. LN1
    ln_k<<<M_TOT, 256>>>(x, g1, be1, h);
    // 2-4. q/k/v projections (q,k with fused elu+1)
    gemm_k<1><<<g1024, 256>>>(h, wq, bq, nullptr, q, M_TOT, DM, DM);
    gemm_k<1><<<g1024, 256>>>(h, wk, bk, nullptr, k, M_TOT, DM, DM);
    gemm_k<0><<<g1024, 256>>>(h, wv, bv, nullptr, v, M_TOT, DM, DM);
    // 5. kv = K^T V per (b,h), deterministic split-S
    kv_partial_k<<<dim3(64, 8), 256>>>(k, v, kvp);
    kv_reduce_k<<<1024, 256>>>(kvp, kv);
    // 6. attn = q @ kv
    attn_k<<<dim3(64, 64), 256>>>(q, kv, attn);
    // 7. out proj + residual with original x
    gemm_k<2><<<g1024, 256>>>(attn, wo, bo, x, x1, M_TOT, DM, DM);
    // 8. LN2
    ln_k<<<M_TOT, 256>>>(x1, g2, be2, h);
    // 9. FF1 (N=8192)
    gemm_k<0><<<g8192, 256>>>(h, w1, b1, nullptr, ffb, M_TOT, 2 * DFF_, DM);
    // 10. GEGLU
    geglu_k<<<M_TOT, 256>>>(ffb, gated);
    // 11. FF2 + residual -> d_out
    gemm_k<2><<<g1024, 256>>>(gated, w2, b2, x1, out, M_TOT, DM, DFF_);
}

// round 4
// speedup vs baseline: 2.2429x; 2.2429x over previous
#include <cuda_runtime.h>
#include <cuda_bf16.h>
#include <math.h>
#include <stdint.h>

typedef __nv_bfloat16 bf16;

#define M_TOT   16384
#define DM      1024
#define DFF_    4096
#define MB(x)   ((size_t)(x) * 1048576ull)

// ---------------- scratch (byte offsets) ----------------
#define Q_OFF    MB(0)
#define K_OFF    MB(64)
#define V_OFF    MB(128)
#define X1_OFF   MB(192)
#define HHI_OFF  MB(256)
#define HLO_OFF  MB(288)
#define AHI_OFF  MB(320)
#define ALO_OFF  MB(352)
#define FF_OFF   MB(384)
#define GHI_OFF  MB(896)
#define GLO_OFF  MB(1024)
#define KV_OFF   MB(1152)
#define KVP_OFF  MB(1153)
#define WQH_OFF  MB(1161)
#define WQL_OFF  MB(1163)
#define WKH_OFF  MB(1165)
#define WKL_OFF  MB(1167)
#define WVH_OFF  MB(1169)
#define WVL_OFF  MB(1171)
#define WOH_OFF  MB(1173)
#define WOL_OFF  MB(1175)
#define W1H_OFF  MB(1177)
#define W1L_OFF  MB(1193)
#define W2H_OFF  MB(1209)
#define W2L_OFF  MB(1217)
#define SCR_TOT  MB(1225)

__device__ __align__(1024) unsigned char g_scratch[SCR_TOT];

// ---------------- PTX helpers (all non-'a' ISA) ----------------
__device__ __forceinline__ uint32_t smem_u32(const void* p) {
    uint32_t a;
    asm("{ .reg .u64 t; cvta.to.shared.u64 t, %1; cvt.u32.u64 %0, t; }" : "=r"(a) : "l"(p));
    return a;
}
__device__ __forceinline__ void cp16(uint32_t dst, const void* src) {
    asm volatile("cp.async.cg.shared.global [%0], [%1], 16;" :: "r"(dst), "l"(src) : "memory");
}
#define CP_COMMIT() asm volatile("cp.async.commit_group;" ::: "memory")
#define CP_WAIT(n)  asm volatile("cp.async.wait_group %0;" :: "n"(n) : "memory")

__device__ __forceinline__ void ldm4(uint32_t* r, uint32_t addr) {
    asm volatile("ldmatrix.sync.aligned.m8n8.x4.shared.b16 {%0,%1,%2,%3}, [%4];"
        : "=r"(r[0]), "=r"(r[1]), "=r"(r[2]), "=r"(r[3]) : "r"(addr));
}
__device__ __forceinline__ void mma16816(float* c, const uint32_t* a, const uint32_t* b) {
    asm volatile("mma.sync.aligned.m16n8k16.row.col.f32.bf16.bf16.f32 "
        "{%0,%1,%2,%3}, {%4,%5,%6,%7}, {%8,%9}, {%0,%1,%2,%3};"
        : "+f"(c[0]), "+f"(c[1]), "+f"(c[2]), "+f"(c[3])
        : "r"(a[0]), "r"(a[1]), "r"(a[2]), "r"(a[3]), "r"(b[0]), "r"(b[1]));
}

// smem tile geometry: rows padded to 80B (20 words -> conflict-free ldmatrix)
#define ROWB   80u
#define PIECE  10240u         // 128 rows * 80B
#define STAGEB 40960u         // 4 pieces

// -------- weight transpose+split: W[K x N] fp32 -> hi/lo [N x K] bf16 --------
__global__ void wsplit_k(const float* __restrict__ W,
                         bf16* __restrict__ hi, bf16* __restrict__ lo,
                         int K, int N)
{
    __shared__ float t[32][33];
    int tx = threadIdx.x, ty = threadIdx.y;
    int n0 = blockIdx.x * 32, k0 = blockIdx.y * 32;
    #pragma unroll
    for (int i = 0; i < 4; i++)
        t[ty + i * 8][tx] = W[(size_t)(k0 + ty + i * 8) * N + n0 + tx];
    __syncthreads();
    #pragma unroll
    for (int i = 0; i < 4; i++) {
        float f = t[tx][ty + i * 8];
        bf16 h = __float2bfloat16(f);
        bf16 l = __float2bfloat16(f - __bfloat162float(h));
        size_t o = (size_t)(n0 + ty + i * 8) * K + k0 + tx;
        hi[o] = h; lo[o] = l;
    }
}

// ---------------- layernorm -> bf16 hi/lo ----------------
__global__ __launch_bounds__(256) void ln_k(const float* __restrict__ x,
                                            const float* __restrict__ gamma,
                                            const float* __restrict__ beta,
                                            bf16* __restrict__ hhi, bf16* __restrict__ hlo)
{
    int row = blockIdx.x, tid = threadIdx.x;
    float4 v = ((const float4*)(x + (size_t)row * DM))[tid];
    float s  = v.x + v.y + v.z + v.w;
    float ss = v.x*v.x + v.y*v.y + v.z*v.z + v.w*v.w;
    #pragma unroll
    for (int o = 16; o; o >>= 1) {
        s  += __shfl_xor_sync(0xffffffffu, s,  o);
        ss += __shfl_xor_sync(0xffffffffu, ss, o);
    }
    __shared__ float shs[8], shss[8], smu, srs;
    int w = tid >> 5, lane = tid & 31;
    if (lane == 0) { shs[w] = s; shss[w] = ss; }
    __syncthreads();
    if (tid == 0) {
        float ts = 0.f, tss = 0.f;
        #pragma unroll
        for (int i = 0; i < 8; i++) { ts += shs[i]; tss += shss[i]; }
        float mu  = ts * (1.0f / DM);
        float var = tss * (1.0f / DM) - mu * mu;
        smu = mu; srs = rsqrtf(var + 1e-5f);
    }
    __syncthreads();
    float mu = smu, rs = srs;
    float4 g = ((const float4*)gamma)[tid];
    float4 b = ((const float4*)beta)[tid];
    float o[4] = { (v.x-mu)*rs*g.x + b.x, (v.y-mu)*rs*g.y + b.y,
                   (v.z-mu)*rs*g.z + b.z, (v.w-mu)*rs*g.w + b.w };
    __align__(8) bf16 hb[4], lb[4];
    #pragma unroll
    for (int t = 0; t < 4; t++) {
        hb[t] = __float2bfloat16(o[t]);
        lb[t] = __float2bfloat16(o[t] - __bfloat162float(hb[t]));
    }
    ((uint2*)(hhi + (size_t)row * DM))[tid] = *(uint2*)hb;
    ((uint2*)(hlo + (size_t)row * DM))[tid] = *(uint2*)lb;
}

// ---------------- mma.sync GEMM: C[MxN] = Ahi/lo[MxK] @ (Bhi/lo[NxK])^T -----------
// tile 128x128x32, 8 warps (2x4), warp tile 64x32
// EPI: 0 = +bias, 1 = +bias then elu+1, 2 = +bias +residual
template<int EPI>
__global__ __launch_bounds__(256) void gemm_mma(
    const bf16* __restrict__ Ahi, const bf16* __restrict__ Alo,
    const bf16* __restrict__ Bhi, const bf16* __restrict__ Blo,
    const float* __restrict__ bias, const float* __restrict__ Rres,
    float* __restrict__ C, int Kdim, int Nout)
{
    extern __shared__ unsigned char dsm[];
    const int tid = threadIdx.x, wid = tid >> 5, lane = tid & 31;
    const int m0 = blockIdx.y * 128, n0 = blockIdx.x * 128;
    const int warp_m = (wid >> 2) * 64, warp_n = (wid & 3) * 32;
    const uint32_t dbase = (smem_u32(dsm) + 1023u) & ~1023u;

    const bf16* srcs[4] = { Ahi, Alo, Bhi, Blo };

    auto fill = [&](int stage, int chunk) {
        uint32_t sb = dbase + (uint32_t)stage * STAGEB;
        int k0 = chunk << 5;
        #pragma unroll
        for (int it = 0; it < 8; it++) {
            int idx = tid + it * 256;          // 0..2047
            int p = idx >> 9, l = idx & 511;
            int row = l >> 2, c = l & 3;
            int grow = ((p < 2) ? m0 : n0) + row;
            cp16(sb + (uint32_t)p * PIECE + (uint32_t)row * ROWB + (uint32_t)c * 16u,
                 srcs[p] + (size_t)grow * Kdim + k0 + c * 8);
        }
    };

    float acc[4][4][4];
    #pragma unroll
    for (int i = 0; i < 4; i++)
        #pragma unroll
        for (int j = 0; j < 4; j++)
            #pragma unroll
            for (int t = 0; t < 4; t++) acc[i][j][t] = 0.f;

    const int nk = Kdim >> 5;
    fill(0, 0); CP_COMMIT();

    for (int c = 0; c < nk; c++) {
        int cur = c & 1;
        if (c + 1 < nk) { fill(1 - cur, c + 1); CP_COMMIT(); CP_WAIT(1); }
        else CP_WAIT(0);
        __syncthreads();

        uint32_t sb = dbase + (uint32_t)cur * STAGEB;
        #pragma unroll
        for (int ks = 0; ks < 2; ks++) {
            // A fragments: [sel][mtile][4]
            uint32_t af[2][4][4];
            {
                int arow = warp_m + (lane & 15);
                uint32_t acol = (uint32_t)(ks * 2 + (lane >> 4)) * 16u;
                #pragma unroll
                for (int sel = 0; sel < 2; sel++)
                    #pragma unroll
                    for (int mt = 0; mt < 4; mt++)
                        ldm4(af[sel][mt],
                             sb + (uint32_t)sel * PIECE + (uint32_t)(arow + mt * 16) * ROWB + acol);
            }
            // B fragments: [sel][ntile][2]
            uint32_t bfr[2][4][2];
            {
                int brow = warp_n + (lane & 7) + ((lane >> 4) * 8);
                uint32_t bcol = (uint32_t)(ks * 2 + ((lane >> 3) & 1)) * 16u;
                #pragma unroll
                for (int sel = 0; sel < 2; sel++)
                    #pragma unroll
                    for (int np = 0; np < 2; np++) {
                        uint32_t r[4];
                        ldm4(r, sb + 2u * PIECE + (uint32_t)sel * PIECE
                               + (uint32_t)(brow + np * 16) * ROWB + bcol);
                        bfr[sel][np * 2 + 0][0] = r[0]; bfr[sel][np * 2 + 0][1] = r[1];
                        bfr[sel][np * 2 + 1][0] = r[2]; bfr[sel][np * 2 + 1][1] = r[3];
                    }
            }
            #pragma unroll
            for (int mt = 0; mt < 4; mt++)
                #pragma unroll
                for (int nt = 0; nt < 4; nt++) {
                    mma16816(acc[mt][nt], af[0][mt], bfr[0][nt]);
                    mma16816(acc[mt][nt], af[0][mt], bfr[1][nt]);
                    mma16816(acc[mt][nt], af[1][mt], bfr[0][nt]);
                }
        }
        __syncthreads();
    }

    // epilogue
    int gid = lane >> 2, tig = lane & 3;
    #pragma unroll
    for (int mt = 0; mt < 4; mt++) {
        int r0 = m0 + warp_m + mt * 16 + gid;
        #pragma unroll
        for (int nt = 0; nt < 4; nt++) {
            int col = n0 + warp_n + nt * 8 + tig * 2;
            float2 bb = *(const float2*)(bias + col);
            float v0 = acc[mt][nt][0] + bb.x, v1 = acc[mt][nt][1] + bb.y;
            float v2 = acc[mt][nt][2] + bb.x, v3 = acc[mt][nt][3] + bb.y;
            if (EPI == 1) {
                v0 = (v0 > 0.f) ? (v0 + 1.f) : expf(v0);
                v1 = (v1 > 0.f) ? (v1 + 1.f) : expf(v1);
                v2 = (v2 > 0.f) ? (v2 + 1.f) : expf(v2);
                v3 = (v3 > 0.f) ? (v3 + 1.f) : expf(v3);
            }
            size_t o0 = (size_t)r0 * Nout + col;
            size_t o1 = (size_t)(r0 + 8) * Nout + col;
            if (EPI == 2) {
                float2 ra = *(const float2*)(Rres + o0);
                float2 rb = *(const float2*)(Rres + o1);
                v0 += ra.x; v1 += ra.y; v2 += rb.x; v3 += rb.y;
            }
            *(float2*)(C + o0) = make_float2(v0, v1);
            *(float2*)(C + o1) = make_float2(v2, v3);
        }
    }
}

// ---------------- kv = K^T V per (b,h), split over S ----------------
__global__ __launch_bounds__(256) void kv_partial_k(const float* __restrict__ Kp,
                                                    const float* __restrict__ Vp,
                                                    float* __restrict__ kvp)
{
    int bh = blockIdx.x, spi = blockIdx.y;
    int b = bh >> 4, h = bh & 15;
    int tid = threadIdx.x;
    __shared__ float ks[32][64], vs[32][64];
    float acc[4][4] = {};
    int d0 = (tid >> 4) * 4, e0 = (tid & 15) * 4;
    size_t base = ((size_t)b * 4096) * DM + h * 64;
    for (int s0 = spi * 512; s0 < spi * 512 + 512; s0 += 32) {
        #pragma unroll
        for (int i = 0; i < 2; i++) {
            int f = tid + i * 256;
            int r = f >> 4, c = (f & 15) * 4;
            size_t off = base + (size_t)(s0 + r) * DM + c;
            *(float4*)&ks[r][c] = *(const float4*)(Kp + off);
            *(float4*)&vs[r][c] = *(const float4*)(Vp + off);
        }
        __syncthreads();
        #pragma unroll
        for (int ssm = 0; ssm < 32; ssm++) {
            float kd[4] = { ks[ssm][d0], ks[ssm][d0+1], ks[ssm][d0+2], ks[ssm][d0+3] };
            float ve[4] = { vs[ssm][e0], vs[ssm][e0+1], vs[ssm][e0+2], vs[ssm][e0+3] };
            #pragma unroll
            for (int i = 0; i < 4; i++)
                #pragma unroll
                for (int j = 0; j < 4; j++) acc[i][j] += kd[i] * ve[j];
        }
        __syncthreads();
    }
    float* outp = kvp + ((size_t)spi * 64 + bh) * 4096;
    #pragma unroll
    for (int i = 0; i < 4; i++)
        *(float4*)(outp + (d0 + i) * 64 + e0) = make_float4(acc[i][0], acc[i][1], acc[i][2], acc[i][3]);
}

__global__ __launch_bounds__(256) void kv_reduce_k(const float* __restrict__ kvp,
                                                   float* __restrict__ kv)
{
    int i = blockIdx.x * 256 + threadIdx.x;
    float s = 0.f;
    #pragma unroll
    for (int spi = 0; spi < 8; spi++) s += kvp[(size_t)spi * 262144 + i];
    kv[i] = s;
}

// ---------------- attn = q @ kv per (b,h), out -> bf16 hi/lo ----------------
__global__ __launch_bounds__(256) void attn_k(const float* __restrict__ Q,
                                              const float* __restrict__ KV,
                                              bf16* __restrict__ Ohi, bf16* __restrict__ Olo)
{
    int bh = blockIdx.x, st = blockIdx.y;
    int b = bh >> 4, h = bh & 15;
    int tid = threadIdx.x;
    __shared__ float kvs[64][64], qs[64][68];
    const float* kvsrc = KV + (size_t)bh * 4096;
    #pragma unroll
    for (int i = 0; i < 4; i++) {
        int f = tid + i * 256;
        int r = f >> 4, c = (f & 15) * 4;
        *(float4*)&kvs[r][c] = *(const float4*)(kvsrc + r * 64 + c);
    }
    size_t qbase = ((size_t)b * 4096 + st * 64) * DM + h * 64;
    #pragma unroll
    for (int i = 0; i < 4; i++) {
        int f = tid + i * 256;
        int r = f >> 4, c = (f & 15) * 4;
        *(float4*)&qs[r][c] = *(const float4*)(Q + qbase + (size_t)r * DM + c);
    }
    __syncthreads();
    int r = tid >> 2, e0 = (tid & 3) * 16;
    float acc[16] = {};
    #pragma unroll 8
    for (int d = 0; d < 64; d++) {
        float qd = qs[r][d];
        #pragma unroll
        for (int j = 0; j < 16; j++) acc[j] += qd * kvs[d][e0 + j];
    }
    size_t obase = qbase + (size_t)r * DM + e0;
    #pragma unroll
    for (int j = 0; j < 16; j++) {
        bf16 hbv = __float2bfloat16(acc[j]);
        Ohi[obase + j] = hbv;
        Olo[obase + j] = __float2bfloat16(acc[j] - __bfloat162float(hbv));
    }
}

// ---------------- geglu: gated = gelu(ff[:, :4096]) * ff[:, 4096:] -> hi/lo ------
__global__ __launch_bounds__(256) void geglu_k(const float* __restrict__ ff,
                                               bf16* __restrict__ ghi, bf16* __restrict__ glo)
{
    size_t m = blockIdx.x;
    int tid = threadIdx.x;
    const float4* gp = (const float4*)(ff + m * 8192);
    const float4* lp = (const float4*)(ff + m * 8192 + 4096);
    const float is2 = 0.70710678118654752f;
    #pragma unroll
    for (int i = 0; i < 4; i++) {
        int idx = tid + i * 256;
        float4 g = gp[idx], l = lp[idx];
        float o[4] = { 0.5f * g.x * (1.f + erff(g.x * is2)) * l.x,
                       0.5f * g.y * (1.f + erff(g.y * is2)) * l.y,
                       0.5f * g.z * (1.f + erff(g.z * is2)) * l.z,
                       0.5f * g.w * (1.f + erff(g.w * is2)) * l.w };
        __align__(8) bf16 hb[4], lb[4];
        #pragma unroll
        for (int t = 0; t < 4; t++) {
            hb[t] = __float2bfloat16(o[t]);
            lb[t] = __float2bfloat16(o[t] - __bfloat162float(hb[t]));
        }
        ((uint2*)(ghi + m * 4096))[idx] = *(uint2*)hb;
        ((uint2*)(glo + m * 4096))[idx] = *(uint2*)lb;
    }
}

// ---------------- launch ----------------
extern "C" void kernel_launch(void* const* d_in, const int* in_sizes, int n_in,
                              void* d_out, int out_size)
{
    const float* x   = (const float*)d_in[0];
    const float* wq  = (const float*)d_in[1];
    const float* bq  = (const float*)d_in[2];
    const float* wk  = (const float*)d_in[3];
    const float* bk  = (const float*)d_in[4];
    const float* wv  = (const float*)d_in[5];
    const float* bv  = (const float*)d_in[6];
    const float* wo  = (const float*)d_in[7];
    const float* bo  = (const float*)d_in[8];
    const float* w1  = (const float*)d_in[9];
    const float* b1  = (const float*)d_in[10];
    const float* w2  = (const float*)d_in[11];
    const float* b2  = (const float*)d_in[12];
    const float* g1  = (const float*)d_in[13];
    const float* be1 = (const float*)d_in[14];
    const float* g2  = (const float*)d_in[15];
    const float* be2 = (const float*)d_in[16];
    float* out = (float*)d_out;

    void* sp = nullptr;
    cudaGetSymbolAddress(&sp, g_scratch);
    unsigned char* S = (unsigned char*)sp;
    float* Qb   = (float*)(S + Q_OFF);
    float* Kb   = (float*)(S + K_OFF);
    float* Vb   = (float*)(S + V_OFF);
    float* X1   = (float*)(S + X1_OFF);
    bf16*  HHI  = (bf16*)(S + HHI_OFF);
    bf16*  HLO  = (bf16*)(S + HLO_OFF);
    bf16*  AHI  = (bf16*)(S + AHI_OFF);
    bf16*  ALO  = (bf16*)(S + ALO_OFF);
    float* FF   = (float*)(S + FF_OFF);
    bf16*  GHI  = (bf16*)(S + GHI_OFF);
    bf16*  GLO  = (bf16*)(S + GLO_OFF);
    float* KVb  = (float*)(S + KV_OFF);
    float* KVP  = (float*)(S + KVP_OFF);
    bf16 *WQH=(bf16*)(S+WQH_OFF), *WQL=(bf16*)(S+WQL_OFF);
    bf16 *WKH=(bf16*)(S+WKH_OFF), *WKL=(bf16*)(S+WKL_OFF);
    bf16 *WVH=(bf16*)(S+WVH_OFF), *WVL=(bf16*)(S+WVL_OFF);
    bf16 *WOH=(bf16*)(S+WOH_OFF), *WOL=(bf16*)(S+WOL_OFF);
    bf16 *W1H=(bf16*)(S+W1H_OFF), *W1L=(bf16*)(S+W1L_OFF);
    bf16 *W2H=(bf16*)(S+W2H_OFF), *W2L=(bf16*)(S+W2L_OFF);

    const int SMEM_GEMM = 2 * STAGEB + 1024;  // 82944
    static bool attr_done = false;
    if (!attr_done) {
        cudaFuncSetAttribute(gemm_mma<0>, cudaFuncAttributeMaxDynamicSharedMemorySize, SMEM_GEMM);
        cudaFuncSetAttribute(gemm_mma<1>, cudaFuncAttributeMaxDynamicSharedMemorySize, SMEM_GEMM);
        cudaFuncSetAttribute(gemm_mma<2>, cudaFuncAttributeMaxDynamicSharedMemorySize, SMEM_GEMM);
        attr_done = true;
    }

    dim3 wb(32, 8);
    wsplit_k<<<dim3(32, 32), wb>>>(wq, WQH, WQL, DM, DM);
    wsplit_k<<<dim3(32, 32), wb>>>(wk, WKH, WKL, DM, DM);
    wsplit_k<<<dim3(32, 32), wb>>>(wv, WVH, WVL, DM, DM);
    wsplit_k<<<dim3(32, 32), wb>>>(wo, WOH, WOL, DM, DM);
    wsplit_k<<<dim3(256, 32), wb>>>(w1, W1H, W1L, DM, 2 * DFF_);
    wsplit_k<<<dim3(32, 128), wb>>>(w2, W2H, W2L, DFF_, DM);

    dim3 gN1024(8, 128), gN8192(64, 128);

    // LN1
    ln_k<<<M_TOT, 256>>>(x, g1, be1, HHI, HLO);
    // q/k/v projections (q,k fused elu+1)
    gemm_mma<1><<<gN1024, 256, SMEM_GEMM>>>(HHI, HLO, WQH, WQL, bq, nullptr, Qb, DM, DM);
    gemm_mma<1><<<gN1024, 256, SMEM_GEMM>>>(HHI, HLO, WKH, WKL, bk, nullptr, Kb, DM, DM);
    gemm_mma<0><<<gN1024, 256, SMEM_GEMM>>>(HHI, HLO, WVH, WVL, bv, nullptr, Vb, DM, DM);
    // linear attention
    kv_partial_k<<<dim3(64, 8), 256>>>(Kb, Vb, KVP);
    kv_reduce_k<<<1024, 256>>>(KVP, KVb);
    attn_k<<<dim3(64, 64), 256>>>(Qb, KVb, AHI, ALO);
    // out proj + residual(x)
    gemm_mma<2><<<gN1024, 256, SMEM_GEMM>>>(AHI, ALO, WOH, WOL, bo, x, X1, DM, DM);
    // LN2
    ln_k<<<M_TOT, 256>>>(X1, g2, be2, HHI, HLO);
    // FF1
    gemm_mma<0><<<gN8192, 256, SMEM_GEMM>>>(HHI, HLO, W1H, W1L, b1, nullptr, FF, DM, 2 * DFF_);
    // GEGLU
    geglu_k<<<M_TOT, 256>>>(FF, GHI, GLO);
    // FF2 + residual(X1)
    gemm_mma<2><<<gN1024, 256, SMEM_GEMM>>>(GHI, GLO, W2H, W2L, b2, X1, out, DFF_, DM);
}

// round 5
// speedup vs baseline: 2.4214x; 1.0796x over previous
#include <cuda_runtime.h>
#include <cuda_bf16.h>
#include <math.h>
#include <stdint.h>

typedef __nv_bfloat16 bf16;

#define M_TOT   16384
#define DM      1024
#define DFF_    4096
#define MB(x)   ((size_t)(x) * 1048576ull)

// ---------------- scratch (byte offsets) ----------------
#define Q_OFF    MB(0)
#define K_OFF    MB(64)
#define V_OFF    MB(128)
#define X1_OFF   MB(192)
#define HHI_OFF  MB(256)
#define HLO_OFF  MB(288)
#define AHI_OFF  MB(320)
#define ALO_OFF  MB(352)
#define GHI_OFF  MB(384)
#define GLO_OFF  MB(512)
#define KV_OFF   MB(640)
#define KVP_OFF  MB(641)
#define WQH_OFF  MB(649)
#define WQL_OFF  MB(651)
#define WKH_OFF  MB(653)
#define WKL_OFF  MB(655)
#define WVH_OFF  MB(657)
#define WVL_OFF  MB(659)
#define WOH_OFF  MB(661)
#define WOL_OFF  MB(663)
#define W1H_OFF  MB(665)
#define W1L_OFF  MB(681)
#define W2H_OFF  MB(697)
#define W2L_OFF  MB(705)
#define SCR_TOT  MB(713)

__device__ __align__(1024) unsigned char g_scratch[SCR_TOT];

// ---------------- PTX helpers (non-'a' ISA only) ----------------
__device__ __forceinline__ uint32_t smem_u32(const void* p) {
    uint32_t a;
    asm("{ .reg .u64 t; cvta.to.shared.u64 t, %1; cvt.u32.u64 %0, t; }" : "=r"(a) : "l"(p));
    return a;
}
__device__ __forceinline__ void cp16(uint32_t dst, const void* src) {
    asm volatile("cp.async.cg.shared.global [%0], [%1], 16;" :: "r"(dst), "l"(src) : "memory");
}
#define CP_COMMIT() asm volatile("cp.async.commit_group;" ::: "memory")
#define CP_WAIT(n)  asm volatile("cp.async.wait_group %0;" :: "n"(n) : "memory")

__device__ __forceinline__ void ldm4(uint32_t* r, uint32_t addr) {
    asm volatile("ldmatrix.sync.aligned.m8n8.x4.shared.b16 {%0,%1,%2,%3}, [%4];"
        : "=r"(r[0]), "=r"(r[1]), "=r"(r[2]), "=r"(r[3]) : "r"(addr));
}
__device__ __forceinline__ void mma16816(float* c, const uint32_t* a, const uint32_t* b) {
    asm volatile("mma.sync.aligned.m16n8k16.row.col.f32.bf16.bf16.f32 "
        "{%0,%1,%2,%3}, {%4,%5,%6,%7}, {%8,%9}, {%0,%1,%2,%3};"
        : "+f"(c[0]), "+f"(c[1]), "+f"(c[2]), "+f"(c[3])
        : "r"(a[0]), "r"(a[1]), "r"(a[2]), "r"(a[3]), "r"(b[0]), "r"(b[1]));
}
__device__ __forceinline__ uint32_t packbf(float a, float b) {
    __nv_bfloat162 t = __floats2bfloat162_rn(a, b);
    return *(uint32_t*)&t;
}

// smem tile geometry: rows padded to 80B (conflict-free ldmatrix, no swizzle)
#define ROWB    80u
#define APIECE  10240u        // 128 rows * 80B
#define BPIECE  20480u        // 256 rows * 80B
#define STAGEB  61440u        // Ahi,Alo,Bhi,Blo
#define SMEM_GEMM (2 * 61440)

// -------- weight transpose+split: W[K x N] fp32 -> hi/lo [N x K] bf16 --------
__global__ void wsplit_k(const float* __restrict__ W,
                         bf16* __restrict__ hi, bf16* __restrict__ lo,
                         int K, int N)
{
    __shared__ float t[32][33];
    int tx = threadIdx.x, ty = threadIdx.y;
    int n0 = blockIdx.x * 32, k0 = blockIdx.y * 32;
    #pragma unroll
    for (int i = 0; i < 4; i++)
        t[ty + i * 8][tx] = W[(size_t)(k0 + ty + i * 8) * N + n0 + tx];
    __syncthreads();
    #pragma unroll
    for (int i = 0; i < 4; i++) {
        float f = t[tx][ty + i * 8];
        bf16 h = __float2bfloat16(f);
        bf16 l = __float2bfloat16(f - __bfloat162float(h));
        size_t o = (size_t)(n0 + ty + i * 8) * K + k0 + tx;
        hi[o] = h; lo[o] = l;
    }
}

// packed variant for W1: interleave 8 gate cols / 8 lin cols per 16 dst rows
__global__ void wsplit_pack_k(const float* __restrict__ W,
                              bf16* __restrict__ hi, bf16* __restrict__ lo,
                              int K, int N)
{
    __shared__ float t[32][33];
    int tx = threadIdx.x, ty = threadIdx.y;
    int n0 = blockIdx.x * 32, k0 = blockIdx.y * 32;
    #pragma unroll
    for (int i = 0; i < 4; i++)
        t[ty + i * 8][tx] = W[(size_t)(k0 + ty + i * 8) * N + n0 + tx];
    __syncthreads();
    #pragma unroll
    for (int i = 0; i < 4; i++) {
        int n = n0 + ty + i * 8;
        int dr = (n < 4096) ? ((n >> 3) * 16 + (n & 7))
                            : (((n - 4096) >> 3) * 16 + 8 + (n & 7));
        float f = t[tx][ty + i * 8];
        bf16 h = __float2bfloat16(f);
        bf16 l = __float2bfloat16(f - __bfloat162float(h));
        size_t o = (size_t)dr * K + k0 + tx;
        hi[o] = h; lo[o] = l;
    }
}

// ---------------- layernorm -> bf16 hi/lo ----------------
__global__ __launch_bounds__(256) void ln_k(const float* __restrict__ x,
                                            const float* __restrict__ gamma,
                                            const float* __restrict__ beta,
                                            bf16* __restrict__ hhi, bf16* __restrict__ hlo)
{
    int row = blockIdx.x, tid = threadIdx.x;
    float4 v = ((const float4*)(x + (size_t)row * DM))[tid];
    float s  = v.x + v.y + v.z + v.w;
    float ss = v.x*v.x + v.y*v.y + v.z*v.z + v.w*v.w;
    #pragma unroll
    for (int o = 16; o; o >>= 1) {
        s  += __shfl_xor_sync(0xffffffffu, s,  o);
        ss += __shfl_xor_sync(0xffffffffu, ss, o);
    }
    __shared__ float shs[8], shss[8], smu, srs;
    int w = tid >> 5, lane = tid & 31;
    if (lane == 0) { shs[w] = s; shss[w] = ss; }
    __syncthreads();
    if (tid == 0) {
        float ts = 0.f, tss = 0.f;
        #pragma unroll
        for (int i = 0; i < 8; i++) { ts += shs[i]; tss += shss[i]; }
        float mu  = ts * (1.0f / DM);
        float var = tss * (1.0f / DM) - mu * mu;
        smu = mu; srs = rsqrtf(var + 1e-5f);
    }
    __syncthreads();
    float mu = smu, rs = srs;
    float4 g = ((const float4*)gamma)[tid];
    float4 b = ((const float4*)beta)[tid];
    float o[4] = { (v.x-mu)*rs*g.x + b.x, (v.y-mu)*rs*g.y + b.y,
                   (v.z-mu)*rs*g.z + b.z, (v.w-mu)*rs*g.w + b.w };
    __align__(8) bf16 hb[4], lb[4];
    #pragma unroll
    for (int t = 0; t < 4; t++) {
        hb[t] = __float2bfloat16(o[t]);
        lb[t] = __float2bfloat16(o[t] - __bfloat162float(hb[t]));
    }
    ((uint2*)(hhi + (size_t)row * DM))[tid] = *(uint2*)hb;
    ((uint2*)(hlo + (size_t)row * DM))[tid] = *(uint2*)lb;
}

// ---------------- mma.sync GEMM: tile 128x256, warp tile 64x64 -------------------
// EPI: 0 = +bias, 1 = +bias,elu+1, 2 = +bias,+residual, 3 = geglu -> bf16 hi/lo
template<int EPI>
__global__ __launch_bounds__(256) void gemm_mma(
    const bf16* __restrict__ Ahi, const bf16* __restrict__ Alo,
    const bf16* __restrict__ Bhi, const bf16* __restrict__ Blo,
    const float* __restrict__ bias, const float* __restrict__ Rres,
    float* __restrict__ C, bf16* __restrict__ Ghi, bf16* __restrict__ Glo,
    int Kdim, int Nout)
{
    extern __shared__ unsigned char dsm[];
    const int tid = threadIdx.x, wid = tid >> 5, lane = tid & 31;
    const int m0 = blockIdx.y * 128, n0 = blockIdx.x * 256;
    const int warp_m = (wid >> 2) * 64, warp_n = (wid & 3) * 64;
    const uint32_t dbase = smem_u32(dsm);

    auto fill = [&](int stage, int chunk) {
        uint32_t sb = dbase + (uint32_t)stage * STAGEB;
        int k0 = chunk << 5;
        #pragma unroll
        for (int it = 0; it < 12; it++) {
            int idx = tid + it * 256;          // 0..3071
            if (idx < 1024) {
                int sel = idx >> 9, l = idx & 511;
                int row = l >> 2, c = l & 3;
                const bf16* src = sel ? Alo : Ahi;
                cp16(sb + (uint32_t)sel * APIECE + (uint32_t)row * ROWB + (uint32_t)c * 16u,
                     src + (size_t)(m0 + row) * Kdim + k0 + c * 8);
            } else {
                int ib = idx - 1024;
                int sel = ib >> 10, l = ib & 1023;
                int row = l >> 2, c = l & 3;
                const bf16* src = sel ? Blo : Bhi;
                cp16(sb + 2u * APIECE + (uint32_t)sel * BPIECE + (uint32_t)row * ROWB + (uint32_t)c * 16u,
                     src + (size_t)(n0 + row) * Kdim + k0 + c * 8);
            }
        }
    };

    float acc[4][8][4];
    #pragma unroll
    for (int i = 0; i < 4; i++)
        #pragma unroll
        for (int j = 0; j < 8; j++)
            #pragma unroll
            for (int t = 0; t < 4; t++) acc[i][j][t] = 0.f;

    const int nk = Kdim >> 5;
    fill(0, 0); CP_COMMIT();

    for (int c = 0; c < nk; c++) {
        int cur = c & 1;
        if (c + 1 < nk) { fill(1 - cur, c + 1); CP_COMMIT(); CP_WAIT(1); }
        else CP_WAIT(0);
        __syncthreads();

        uint32_t sb = dbase + (uint32_t)cur * STAGEB;
        uint32_t aoff0 = sb, aoff1 = sb + APIECE;
        uint32_t boff0 = sb + 2u * APIECE, boff1 = boff0 + BPIECE;

        #pragma unroll
        for (int ks = 0; ks < 2; ks++) {
            uint32_t af[2][4][4];
            {
                int arow = warp_m + (lane & 15);
                uint32_t acol = (uint32_t)(ks * 2 + (lane >> 4)) * 16u;
                #pragma unroll
                for (int mt = 0; mt < 4; mt++) {
                    ldm4(af[0][mt], aoff0 + (uint32_t)(arow + mt * 16) * ROWB + acol);
                    ldm4(af[1][mt], aoff1 + (uint32_t)(arow + mt * 16) * ROWB + acol);
                }
            }
            int brow = warp_n + (lane & 7) + ((lane >> 4) * 8);
            uint32_t bcol = (uint32_t)(ks * 2 + ((lane >> 3) & 1)) * 16u;
            // B-hi: pair with A-hi and A-lo
            #pragma unroll
            for (int np = 0; np < 4; np++) {
                uint32_t r[4];
                ldm4(r, boff0 + (uint32_t)(brow + np * 16) * ROWB + bcol);
                uint32_t b0[2] = { r[0], r[1] }, b1v[2] = { r[2], r[3] };
                #pragma unroll
                for (int mt = 0; mt < 4; mt++) {
                    mma16816(acc[mt][np * 2 + 0], af[0][mt], b0);
                    mma16816(acc[mt][np * 2 + 1], af[0][mt], b1v);
                    mma16816(acc[mt][np * 2 + 0], af[1][mt], b0);
                    mma16816(acc[mt][np * 2 + 1], af[1][mt], b1v);
                }
            }
            // B-lo: pair with A-hi only
            #pragma unroll
            for (int np = 0; np < 4; np++) {
                uint32_t r[4];
                ldm4(r, boff1 + (uint32_t)(brow + np * 16) * ROWB + bcol);
                uint32_t b0[2] = { r[0], r[1] }, b1v[2] = { r[2], r[3] };
                #pragma unroll
                for (int mt = 0; mt < 4; mt++) {
                    mma16816(acc[mt][np * 2 + 0], af[0][mt], b0);
                    mma16816(acc[mt][np * 2 + 1], af[0][mt], b1v);
                }
            }
        }
        __syncthreads();
    }

    // ---------------- epilogue ----------------
    int gid = lane >> 2, tig = lane & 3;
    if (EPI == 3) {
        const float is2 = 0.70710678118654752f;
        #pragma unroll
        for (int mt = 0; mt < 4; mt++) {
            int r0 = m0 + warp_m + mt * 16 + gid;
            #pragma unroll
            for (int j = 0; j < 4; j++) {
                int rc = ((n0 + warp_n) >> 1) + j * 8 + tig * 2;
                float2 bg = *(const float2*)(bias + rc);
                float2 bl = *(const float2*)(bias + 4096 + rc);
                float gv[4] = { acc[mt][2*j][0] + bg.x, acc[mt][2*j][1] + bg.y,
                                acc[mt][2*j][2] + bg.x, acc[mt][2*j][3] + bg.y };
                float lv[4] = { acc[mt][2*j+1][0] + bl.x, acc[mt][2*j+1][1] + bl.y,
                                acc[mt][2*j+1][2] + bl.x, acc[mt][2*j+1][3] + bl.y };
                float o[4], oh[4], ol[4];
                #pragma unroll
                for (int t = 0; t < 4; t++) {
                    o[t] = 0.5f * gv[t] * (1.f + erff(gv[t] * is2)) * lv[t];
                    bf16 hb = __float2bfloat16(o[t]);
                    oh[t] = __bfloat162float(hb);
                    ol[t] = o[t] - oh[t];
                }
                size_t o0 = (size_t)r0 * 4096 + rc;
                size_t o1 = (size_t)(r0 + 8) * 4096 + rc;
                *(uint32_t*)(Ghi + o0) = packbf(oh[0], oh[1]);
                *(uint32_t*)(Glo + o0) = packbf(ol[0], ol[1]);
                *(uint32_t*)(Ghi + o1) = packbf(oh[2], oh[3]);
                *(uint32_t*)(Glo + o1) = packbf(ol[2], ol[3]);
            }
        }
    } else {
        #pragma unroll
        for (int mt = 0; mt < 4; mt++) {
            int r0 = m0 + warp_m + mt * 16 + gid;
            #pragma unroll
            for (int nt = 0; nt < 8; nt++) {
                int col = n0 + warp_n + nt * 8 + tig * 2;
                float2 bb = *(const float2*)(bias + col);
                float v0 = acc[mt][nt][0] + bb.x, v1 = acc[mt][nt][1] + bb.y;
                float v2 = acc[mt][nt][2] + bb.x, v3 = acc[mt][nt][3] + bb.y;
                if (EPI == 1) {
                    v0 = (v0 > 0.f) ? (v0 + 1.f) : expf(v0);
                    v1 = (v1 > 0.f) ? (v1 + 1.f) : expf(v1);
                    v2 = (v2 > 0.f) ? (v2 + 1.f) : expf(v2);
                    v3 = (v3 > 0.f) ? (v3 + 1.f) : expf(v3);
                }
                size_t o0 = (size_t)r0 * Nout + col;
                size_t o1 = (size_t)(r0 + 8) * Nout + col;
                if (EPI == 2) {
                    float2 ra = *(const float2*)(Rres + o0);
                    float2 rb = *(const float2*)(Rres + o1);
                    v0 += ra.x; v1 += ra.y; v2 += rb.x; v3 += rb.y;
                }
                *(float2*)(C + o0) = make_float2(v0, v1);
                *(float2*)(C + o1) = make_float2(v2, v3);
            }
        }
    }
}

// ---------------- kv = K^T V per (b,h), split over S ----------------
__global__ __launch_bounds__(256) void kv_partial_k(const float* __restrict__ Kp,
                                                    const float* __restrict__ Vp,
                                                    float* __restrict__ kvp)
{
    int bh = blockIdx.x, spi = blockIdx.y;
    int b = bh >> 4, h = bh & 15;
    int tid = threadIdx.x;
    __shared__ float ks[32][64], vs[32][64];
    float acc[4][4] = {};
    int d0 = (tid >> 4) * 4, e0 = (tid & 15) * 4;
    size_t base = ((size_t)b * 4096) * DM + h * 64;
    for (int s0 = spi * 512; s0 < spi * 512 + 512; s0 += 32) {
        #pragma unroll
        for (int i = 0; i < 2; i++) {
            int f = tid + i * 256;
            int r = f >> 4, c = (f & 15) * 4;
            size_t off = base + (size_t)(s0 + r) * DM + c;
            *(float4*)&ks[r][c] = *(const float4*)(Kp + off);
            *(float4*)&vs[r][c] = *(const float4*)(Vp + off);
        }
        __syncthreads();
        #pragma unroll
        for (int ssm = 0; ssm < 32; ssm++) {
            float kd[4] = { ks[ssm][d0], ks[ssm][d0+1], ks[ssm][d0+2], ks[ssm][d0+3] };
            float ve[4] = { vs[ssm][e0], vs[ssm][e0+1], vs[ssm][e0+2], vs[ssm][e0+3] };
            #pragma unroll
            for (int i = 0; i < 4; i++)
                #pragma unroll
                for (int j = 0; j < 4; j++) acc[i][j] += kd[i] * ve[j];
        }
        __syncthreads();
    }
    float* outp = kvp + ((size_t)spi * 64 + bh) * 4096;
    #pragma unroll
    for (int i = 0; i < 4; i++)
        *(float4*)(outp + (d0 + i) * 64 + e0) = make_float4(acc[i][0], acc[i][1], acc[i][2], acc[i][3]);
}

__global__ __launch_bounds__(256) void kv_reduce_k(const float* __restrict__ kvp,
                                                   float* __restrict__ kv)
{
    int i = blockIdx.x * 256 + threadIdx.x;
    float s = 0.f;
    #pragma unroll
    for (int spi = 0; spi < 8; spi++) s += kvp[(size_t)spi * 262144 + i];
    kv[i] = s;
}

// ---------------- attn = q @ kv per (b,h), out -> bf16 hi/lo ----------------
__global__ __launch_bounds__(256) void attn_k(const float* __restrict__ Q,
                                              const float* __restrict__ KV,
                                              bf16* __restrict__ Ohi, bf16* __restrict__ Olo)
{
    int bh = blockIdx.x, st = blockIdx.y;
    int b = bh >> 4, h = bh & 15;
    int tid = threadIdx.x;
    __shared__ float kvs[64][64], qs[64][68];
    const float* kvsrc = KV + (size_t)bh * 4096;
    #pragma unroll
    for (int i = 0; i < 4; i++) {
        int f = tid + i * 256;
        int r = f >> 4, c = (f & 15) * 4;
        *(float4*)&kvs[r][c] = *(const float4*)(kvsrc + r * 64 + c);
    }
    size_t qbase = ((size_t)b * 4096 + st * 64) * DM + h * 64;
    #pragma unroll
    for (int i = 0; i < 4; i++) {
        int f = tid + i * 256;
        int r = f >> 4, c = (f & 15) * 4;
        *(float4*)&qs[r][c] = *(const float4*)(Q + qbase + (size_t)r * DM + c);
    }
    __syncthreads();
    int r = tid >> 2, e0 = (tid & 3) * 16;
    float acc[16] = {};
    #pragma unroll 8
    for (int d = 0; d < 64; d++) {
        float qd = qs[r][d];
        #pragma unroll
        for (int j = 0; j < 16; j++) acc[j] += qd * kvs[d][e0 + j];
    }
    size_t obase = qbase + (size_t)r * DM + e0;
    #pragma unroll
    for (int j = 0; j < 16; j++) {
        bf16 hbv = __float2bfloat16(acc[j]);
        Ohi[obase + j] = hbv;
        Olo[obase + j] = __float2bfloat16(acc[j] - __bfloat162float(hbv));
    }
}

// ---------------- launch ----------------
extern "C" void kernel_launch(void* const* d_in, const int* in_sizes, int n_in,
                              void* d_out, int out_size)
{
    const float* x   = (const float*)d_in[0];
    const float* wq  = (const float*)d_in[1];
    const float* bq  = (const float*)d_in[2];
    const float* wk  = (const float*)d_in[3];
    const float* bk  = (const float*)d_in[4];
    const float* wv  = (const float*)d_in[5];
    const float* bv  = (const float*)d_in[6];
    const float* wo  = (const float*)d_in[7];
    const float* bo  = (const float*)d_in[8];
    const float* w1  = (const float*)d_in[9];
    const float* b1  = (const float*)d_in[10];
    const float* w2  = (const float*)d_in[11];
    const float* b2  = (const float*)d_in[12];
    const float* g1  = (const float*)d_in[13];
    const float* be1 = (const float*)d_in[14];
    const float* g2  = (const float*)d_in[15];
    const float* be2 = (const float*)d_in[16];
    float* out = (float*)d_out;

    void* sp = nullptr;
    cudaGetSymbolAddress(&sp, g_scratch);
    unsigned char* S = (unsigned char*)sp;
    float* Qb   = (float*)(S + Q_OFF);
    float* Kb   = (float*)(S + K_OFF);
    float* Vb   = (float*)(S + V_OFF);
    float* X1   = (float*)(S + X1_OFF);
    bf16*  HHI  = (bf16*)(S + HHI_OFF);
    bf16*  HLO  = (bf16*)(S + HLO_OFF);
    bf16*  AHI  = (bf16*)(S + AHI_OFF);
    bf16*  ALO  = (bf16*)(S + ALO_OFF);
    bf16*  GHI  = (bf16*)(S + GHI_OFF);
    bf16*  GLO  = (bf16*)(S + GLO_OFF);
    float* KVb  = (float*)(S + KV_OFF);
    float* KVP  = (float*)(S + KVP_OFF);
    bf16 *WQH=(bf16*)(S+WQH_OFF), *WQL=(bf16*)(S+WQL_OFF);
    bf16 *WKH=(bf16*)(S+WKH_OFF), *WKL=(bf16*)(S+WKL_OFF);
    bf16 *WVH=(bf16*)(S+WVH_OFF), *WVL=(bf16*)(S+WVL_OFF);
    bf16 *WOH=(bf16*)(S+WOH_OFF), *WOL=(bf16*)(S+WOL_OFF);
    bf16 *W1H=(bf16*)(S+W1H_OFF), *W1L=(bf16*)(S+W1L_OFF);
    bf16 *W2H=(bf16*)(S+W2H_OFF), *W2L=(bf16*)(S+W2L_OFF);

    static bool attr_done = false;
    if (!attr_done) {
        cudaFuncSetAttribute(gemm_mma<0>, cudaFuncAttributeMaxDynamicSharedMemorySize, SMEM_GEMM);
        cudaFuncSetAttribute(gemm_mma<1>, cudaFuncAttributeMaxDynamicSharedMemorySize, SMEM_GEMM);
        cudaFuncSetAttribute(gemm_mma<2>, cudaFuncAttributeMaxDynamicSharedMemorySize, SMEM_GEMM);
        cudaFuncSetAttribute(gemm_mma<3>, cudaFuncAttributeMaxDynamicSharedMemorySize, SMEM_GEMM);
        attr_done = true;
    }

    dim3 wb(32, 8);
    wsplit_k<<<dim3(32, 32), wb>>>(wq, WQH, WQL, DM, DM);
    wsplit_k<<<dim3(32, 32), wb>>>(wk, WKH, WKL, DM, DM);
    wsplit_k<<<dim3(32, 32), wb>>>(wv, WVH, WVL, DM, DM);
    wsplit_k<<<dim3(32, 32), wb>>>(wo, WOH, WOL, DM, DM);
    wsplit_pack_k<<<dim3(256, 32), wb>>>(w1, W1H, W1L, DM, 2 * DFF_);
    wsplit_k<<<dim3(32, 128), wb>>>(w2, W2H, W2L, DFF_, DM);

    dim3 gN1024(4, 128), gN8192(32, 128);

    // LN1
    ln_k<<<M_TOT, 256>>>(x, g1, be1, HHI, HLO);
    // q/k/v projections (q,k fused elu+1)
    gemm_mma<1><<<gN1024, 256, SMEM_GEMM>>>(HHI, HLO, WQH, WQL, bq, nullptr, Qb, nullptr, nullptr, DM, DM);
    gemm_mma<1><<<gN1024, 256, SMEM_GEMM>>>(HHI, HLO, WKH, WKL, bk, nullptr, Kb, nullptr, nullptr, DM, DM);
    gemm_mma<0><<<gN1024, 256, SMEM_GEMM>>>(HHI, HLO, WVH, WVL, bv, nullptr, Vb, nullptr, nullptr, DM, DM);
    // linear attention
    kv_partial_k<<<dim3(64, 8), 256>>>(Kb, Vb, KVP);
    kv_reduce_k<<<1024, 256>>>(KVP, KVb);
    attn_k<<<dim3(64, 64), 256>>>(Qb, KVb, AHI, ALO);
    // out proj + residual(x)
    gemm_mma<2><<<gN1024, 256, SMEM_GEMM>>>(AHI, ALO, WOH, WOL, bo, x, X1, nullptr, nullptr, DM, DM);
    // LN2
    ln_k<<<M_TOT, 256>>>(X1, g2, be2, HHI, HLO);
    // FF1 + fused GEGLU -> bf16 hi/lo
    gemm_mma<3><<<gN8192, 256, SMEM_GEMM>>>(HHI, HLO, W1H, W1L, b1, nullptr, nullptr, GHI, GLO, DM, DFF_);
    // FF2 + residual(X1)
    gemm_mma<2><<<gN1024, 256, SMEM_GEMM>>>(GHI, GLO, W2H, W2L, b2, X1, out, nullptr, nullptr, DFF_, DM);
}